// round 7
// baseline (speedup 1.0000x reference)
#include <cuda_runtime.h>
#include <cuda_bf16.h>
#include <cstdint>
#include <cstddef>

// ---------------------------------------------------------------------------
// Scratch (device globals — no allocation allowed)
// ---------------------------------------------------------------------------
__device__ float g_noise[(size_t)1024 * 131072];       // 512 MiB prescaled gumbel noise
__device__ uint2 g_w1hl[(size_t)1024 * 8192];          // W1 packed hi/lo pairs [k/2][n]
__device__ uint2 g_w2hl[(size_t)4096 * 8192];          // W2
__device__ uint2 g_w3hl[(size_t)4096 * 2048];          // W3
__device__ uint2 g_fhl [64 * 1024];                    // f  packed pairs [m][k/2]
__device__ uint2 g_h1hl[64 * 4096];                    // h1 packed pairs
__device__ uint2 g_h2hl[64 * 4096];                    // h2 packed pairs
__device__ float g_p [64 * 8192];                      // pre-BN GEMM output (g1/g2)
__device__ float g_p3[64 * 2048];                      // pre-BN GEMM output (g3)
__device__ float g_mask0[64 * 2048];
__device__ uint2 g_keys[1024];
__device__ int   g_icnt[1024];                         // per-iteration noise arrivals

// ---------------------------------------------------------------------------
// bf16 pack helpers
// ---------------------------------------------------------------------------
__device__ __forceinline__ uint32_t bfpack(float x0, float x1)
{
    __nv_bfloat162 h = __floats2bfloat162_rn(x0, x1);
    return reinterpret_cast<uint32_t&>(h);
}
__device__ __forceinline__ uint2 hilo_pair(float x0, float x1)
{
    __nv_bfloat16 h0 = __float2bfloat16(x0);
    __nv_bfloat16 h1 = __float2bfloat16(x1);
    float r0 = x0 - __bfloat162float(h0);
    float r1 = x1 - __bfloat162float(h1);
    uint2 o;
    o.x = ((uint32_t)reinterpret_cast<unsigned short&>(h1) << 16)
        | (uint32_t)reinterpret_cast<unsigned short&>(h0);
    o.y = bfpack(r0, r1);
    return o;
}

// mma.sync m16n8k16 row.col bf16 -> f32 (base sm_103, no 'a' features)
__device__ __forceinline__ void mma16816(float* c, const uint32_t* a, const uint32_t* b)
{
    asm volatile("mma.sync.aligned.m16n8k16.row.col.f32.bf16.bf16.f32 "
                 "{%0,%1,%2,%3}, {%4,%5,%6,%7}, {%8,%9}, {%0,%1,%2,%3};"
                 : "+f"(c[0]), "+f"(c[1]), "+f"(c[2]), "+f"(c[3])
                 : "r"(a[0]), "r"(a[1]), "r"(a[2]), "r"(a[3]), "r"(b[0]), "r"(b[1]));
}

// ---------------------------------------------------------------------------
// Threefry-2x32-20 (bit-exact JAX)
// ---------------------------------------------------------------------------
__device__ __forceinline__ void tf_block(uint32_t ks0, uint32_t ks1, uint32_t ks2,
                                         uint32_t x0, uint32_t x1,
                                         uint32_t& o0, uint32_t& o1)
{
    x0 += ks0; x1 += ks1;
#define TFR(r) { x0 += x1; x1 = __funnelshift_l(x1, x1, (r)); x1 ^= x0; }
    TFR(13); TFR(15); TFR(26); TFR(6);
    x0 += ks1; x1 += ks2 + 1u;
    TFR(17); TFR(29); TFR(16); TFR(24);
    x0 += ks2; x1 += ks0 + 2u;
    TFR(13); TFR(15); TFR(26); TFR(6);
    x0 += ks0; x1 += ks1 + 3u;
    TFR(17); TFR(29); TFR(16); TFR(24);
    x0 += ks1; x1 += ks2 + 4u;
    TFR(13); TFR(15); TFR(26); TFR(6);
    x0 += ks2; x1 += ks0 + 5u;
#undef TFR
    o0 = x0; o1 = x1;
}

__global__ void keys_kernel()
{
    int i = threadIdx.x;
    g_icnt[i] = 0;
    uint32_t o0, o1;
    tf_block(0u, 42u, 0u ^ 42u ^ 0x1BD11BDAu, 0u, (uint32_t)i, o0, o1);
    g_keys[i] = make_uint2(o0, o1);
}

__device__ __forceinline__ float bits_to_noise(uint32_t bits)
{
    uint32_t mant = bits >> 9;
    float fl = __uint2float_rn(mant) * 1.1920928955078125e-07f;  // exact m*2^-23
    float L;
    float d = 1.0f - fl;
    if (d <= 0.015625f) {
        L = d * (1.0f + d * (0.5f + d * (0.3333333432674408f + d * 0.25f)));
    } else if (mant == 0u) {
        L = 87.336544750553109f;                                 // -ln(2^-126)
    } else {
        L = -0.69314718055994531f * __log2f(fl);
    }
    return -2.0f * __log2f(L);
}

// One noise block = 2048 elements of iteration i = b>>6, chunk = b&63.
template <int TPB>
__device__ __forceinline__ void noise_body(int b)
{
    const int i = b >> 6;
    const uint2 key = g_keys[i];
    const uint32_t k1 = key.x, k2 = key.y;
    const uint32_t ks2 = k1 ^ k2 ^ 0x1BD11BDAu;
    const uint32_t jbase = (uint32_t)(b & 63) * 2048u + threadIdx.x;
    float* out = g_noise + (size_t)i * 131072u;
#pragma unroll 8
    for (int t = 0; t < 2048 / TPB; t++) {
        uint32_t j = jbase + (uint32_t)t * TPB;
        uint32_t o0, o1;
        tf_block(k1, k2, ks2, 0u, j, o0, o1);
        out[j] = bits_to_noise(o0 ^ o1);
    }
    __syncthreads();
    if (threadIdx.x == 0) {
        __threadfence();
        atomicAdd(&g_icnt[i], 1);
    }
}

// ---------------------------------------------------------------------------
// Prep: convert W1/W2/W3 and f into packed hi/lo bf16 pair layout.
//   W: [K][N] fp32 -> [K/2][N] uint2 {hi(k,k+1), lo(k,k+1)}
//   f: [64][K]     -> [64][K/2] uint2
// Extra CTAs generate gumbel noise.
// ---------------------------------------------------------------------------
template <int N>
__device__ __forceinline__ void conv_w(const float* __restrict__ W, uint2* __restrict__ O,
                                       int total, int t0, int stride)
{
    for (int idx = t0; idx < total; idx += stride) {
        int kp = idx / N;
        int n  = idx - kp * N;
        float w0 = W[(size_t)(2 * kp) * N + n];
        float w1 = W[(size_t)(2 * kp + 1) * N + n];
        O[idx] = hilo_pair(w0, w1);
    }
}

__global__ __launch_bounds__(256) void prep_noise(const float* __restrict__ f,
                                                  const float* __restrict__ W1,
                                                  const float* __restrict__ W2,
                                                  const float* __restrict__ W3,
                                                  int nPrep, int noiseBase)
{
    if (blockIdx.x >= nPrep) { noise_body<256>(noiseBase + (int)blockIdx.x - nPrep); return; }
    const int t0 = blockIdx.x * 256 + threadIdx.x;
    const int stride = nPrep * 256;

    conv_w<8192>(W2, g_w2hl, 4096 * 8192, t0, stride);
    conv_w<8192>(W1, g_w1hl, 1024 * 8192, t0, stride);
    conv_w<2048>(W3, g_w3hl, 4096 * 2048, t0, stride);

    for (int idx = t0; idx < 64 * 1024; idx += stride) {
        int m = idx >> 10, kp = idx & 1023;
        float x0 = f[m * 2048 + 2 * kp];
        float x1 = f[m * 2048 + 2 * kp + 1];
        g_fhl[idx] = hilo_pair(x0, x1);
    }
}

// ---------------------------------------------------------------------------
// HMMA GEMM: 64 x N, CTA tile 64x64, 8 warps = 2M(32) x 4N(16), no smem.
// A: [64][K/2] uint2 packed pairs; B: [K/2][N] uint2. 4-pass split product.
// Writes pre-BN fp32 P. Extra CTAs generate noise.
// ---------------------------------------------------------------------------
__global__ __launch_bounds__(256) void gemm_mma(const uint2* __restrict__ Ahl,
                                                const uint2* __restrict__ Bhl,
                                                float* __restrict__ P,
                                                int K, int N, int nGemm, int noiseBase)
{
    if (blockIdx.x >= nGemm) { noise_body<256>(noiseBase + (int)blockIdx.x - nGemm); return; }

    const int tid  = threadIdx.x;
    const int lane = tid & 31, wid = tid >> 5;
    const int mg = wid & 1;              // M group: rows mg*32 + {0,16}
    const int ng = wid >> 1;             // N group: cols ng*16 + {0,8}
    const int cb = (int)blockIdx.x * 64;
    const int q  = lane & 3, l4 = lane >> 2;
    const int KP = K >> 1;

    const int r0 = mg * 32 + l4;
    const uint2* A0 = Ahl + (size_t)(r0)      * KP;
    const uint2* A1 = Ahl + (size_t)(r0 + 8)  * KP;
    const uint2* A2 = Ahl + (size_t)(r0 + 16) * KP;
    const uint2* A3 = Ahl + (size_t)(r0 + 24) * KP;
    const int n0 = cb + ng * 16 + l4;
    const uint2* B0 = Bhl + n0;
    const uint2* B1 = Bhl + n0 + 8;

    float acc[2][2][4] = {};             // [mfrag][nfrag][4]

    for (int kp = q; kp < KP; kp += 8) {
        // A fragments (mfrag 0: rows r0/r0+8; mfrag 1: +16). LDG.64 each.
        const uint2 xa0 = A0[kp], xa1 = A1[kp], xa2 = A0[kp + 4], xa3 = A1[kp + 4];
        const uint2 ya0 = A2[kp], ya1 = A3[kp], ya2 = A2[kp + 4], ya3 = A3[kp + 4];
        // B fragments (nfrag 0/1)
        const size_t bo0 = (size_t)kp * N, bo1 = (size_t)(kp + 4) * N;
        const uint2 b00 = B0[bo0], b01 = B0[bo1];
        const uint2 b10 = B1[bo0], b11 = B1[bo1];

        const uint32_t ah0[4] = {xa0.x, xa1.x, xa2.x, xa3.x};
        const uint32_t al0[4] = {xa0.y, xa1.y, xa2.y, xa3.y};
        const uint32_t ah1[4] = {ya0.x, ya1.x, ya2.x, ya3.x};
        const uint32_t al1[4] = {ya0.y, ya1.y, ya2.y, ya3.y};
        const uint32_t bh0[2] = {b00.x, b01.x};
        const uint32_t bl0[2] = {b00.y, b01.y};
        const uint32_t bh1[2] = {b10.x, b11.x};
        const uint32_t bl1[2] = {b10.y, b11.y};

        mma16816(acc[0][0], ah0, bh0); mma16816(acc[0][0], ah0, bl0);
        mma16816(acc[0][0], al0, bh0); mma16816(acc[0][0], al0, bl0);
        mma16816(acc[0][1], ah0, bh1); mma16816(acc[0][1], ah0, bl1);
        mma16816(acc[0][1], al0, bh1); mma16816(acc[0][1], al0, bl1);
        mma16816(acc[1][0], ah1, bh0); mma16816(acc[1][0], ah1, bl0);
        mma16816(acc[1][0], al1, bh0); mma16816(acc[1][0], al1, bl0);
        mma16816(acc[1][1], ah1, bh1); mma16816(acc[1][1], ah1, bl1);
        mma16816(acc[1][1], al1, bh1); mma16816(acc[1][1], al1, bl1);
    }

#pragma unroll
    for (int mf = 0; mf < 2; mf++) {
        const int rb = mg * 32 + mf * 16 + l4;
#pragma unroll
        for (int nf = 0; nf < 2; nf++) {
            const int cc = cb + ng * 16 + nf * 8 + 2 * q;
            *(float2*)(P + (size_t)rb * N + cc)       = make_float2(acc[mf][nf][0], acc[mf][nf][1]);
            *(float2*)(P + (size_t)(rb + 8) * N + cc) = make_float2(acc[mf][nf][2], acc[mf][nf][3]);
        }
    }
}

// ---------------------------------------------------------------------------
// bias + batch-BN (+ affine + ReLU). Each thread owns 2 adjacent columns.
// AR=true  -> emit packed hi/lo bf16 pairs (next GEMM's A operand).
// AR=false -> emit fp32 mask0. Extra CTAs = noise.
// ---------------------------------------------------------------------------
template <bool AR, int RED>
__global__ __launch_bounds__(256) void reduce_noise(const float* __restrict__ P,
                                                    const float* __restrict__ bias,
                                                    const float* __restrict__ gamma,
                                                    const float* __restrict__ beta,
                                                    uint2* __restrict__ AhlOut,
                                                    float* __restrict__ Yout,
                                                    int N, int noiseBase)
{
    if (blockIdx.x >= RED) { noise_body<256>(noiseBase + (int)blockIdx.x - RED); return; }

    const int cp = blockIdx.x * 256 + threadIdx.x;   // column-pair index
    const int c0 = cp * 2;
    const float b0 = bias[c0], b1 = bias[c0 + 1];
    float s0 = 0.f, ss0 = 0.f, s1 = 0.f, ss1 = 0.f;
#pragma unroll 4
    for (int r = 0; r < 64; r++) {
        float2 v = *(const float2*)(P + (size_t)r * N + c0);
        float v0 = v.x + b0, v1 = v.y + b1;
        s0 += v0; ss0 += v0 * v0;
        s1 += v1; ss1 += v1 * v1;
    }
    const float m0 = s0 * 0.015625f, m1 = s1 * 0.015625f;
    const float i0 = rsqrtf(fmaf(-m0, m0, ss0 * 0.015625f) + 1e-5f);
    const float i1 = rsqrtf(fmaf(-m1, m1, ss1 * 0.015625f) + 1e-5f);
    const float ga0 = AR ? gamma[c0] : 1.0f, ga1 = AR ? gamma[c0 + 1] : 1.0f;
    const float be0 = AR ? beta[c0]  : 0.0f, be1 = AR ? beta[c0 + 1]  : 0.0f;
#pragma unroll 4
    for (int r = 0; r < 64; r++) {
        float2 v = *(const float2*)(P + (size_t)r * N + c0);
        float y0 = (v.x + b0 - m0) * i0;
        float y1 = (v.y + b1 - m1) * i1;
        if (AR) {
            y0 = fmaxf(fmaf(y0, ga0, be0), 0.0f);
            y1 = fmaxf(fmaf(y1, ga1, be1), 0.0f);
            AhlOut[(size_t)r * (N >> 1) + cp] = hilo_pair(y0, y1);
        } else {
            *(float2*)(Yout + (size_t)r * N + c0) = make_float2(y0, y1);
        }
    }
}

// ---------------------------------------------------------------------------
// Iteration kernel (+ noise tail for iterations >= 875).
// ---------------------------------------------------------------------------
__device__ __forceinline__ float ex2f(float x)
{
    float y; asm("ex2.approx.f32 %0, %1;" : "=f"(y) : "f"(x)); return y;
}

__global__ __launch_bounds__(512) void iter_noise(float* __restrict__ zout, int noiseBase)
{
    if (blockIdx.x >= 64) { noise_body<512>(noiseBase + (int)blockIdx.x - 64); return; }

    const int row  = blockIdx.x;
    const int tid  = threadIdx.x;
    const int lane = tid & 31, wid = tid >> 5;
    const float C = 2.8853900817779268f;   // 2*log2(e)

    float4 m = *(const float4*)(g_mask0 + row * 2048 + 4 * tid);
    float4 z = make_float4(0.f, 0.f, 0.f, 0.f);

    __shared__ float wsum[2][16];
    volatile int* icnt = (volatile int*)g_icnt;

    const float4* np = (const float4*)g_noise + (size_t)row * 512 + tid;

    float4 nx = np[0];
    for (int i = 0; i < 1024; i++) {
        const float4 cur = nx;
        if (i < 1023) nx = np[(size_t)(i + 1) * 32768];

        const float e0 = ex2f(fmaf(m.x, C, cur.x));
        const float e1 = ex2f(fmaf(m.y, C, cur.y));
        const float e2 = ex2f(fmaf(m.z, C, cur.z));
        const float e3 = ex2f(fmaf(m.w, C, cur.w));
        float s = (e0 + e1) + (e2 + e3);
#pragma unroll
        for (int o = 16; o; o >>= 1) s += __shfl_xor_sync(0xffffffffu, s, o);
        if (lane == 0) wsum[i & 1][wid] = s;

        // readiness gate for the in-flight tail (iterations >= 875)
        if (tid == 0 && (i & 7) == 0 && i >= 840) {
            const int wend = (i + 33 < 1023) ? i + 33 : 1023;
            for (int w = i + 1; w <= wend; w++)
                while (icnt[w] < 64) {}
            __threadfence();
        }
        __syncthreads();

        const float4* wp = (const float4*)wsum[i & 1];
        const float4 t0 = wp[0], t1 = wp[1], t2 = wp[2], t3 = wp[3];
        const float t = (((t0.x + t0.y) + (t0.z + t0.w)) + ((t1.x + t1.y) + (t1.z + t1.w)))
                      + (((t2.x + t2.y) + (t2.z + t2.w)) + ((t3.x + t3.y) + (t3.z + t3.w)));
        float r; asm("rcp.approx.f32 %0, %1;" : "=f"(r) : "f"(t));
        m.x = e0 * r; m.y = e1 * r; m.z = e2 * r; m.w = e3 * r;
        z.x = fmaxf(z.x, m.x); z.y = fmaxf(z.y, m.y);
        z.z = fmaxf(z.z, m.z); z.w = fmaxf(z.w, m.w);
    }
    *(float4*)(zout + row * 2048 + 4 * tid) = z;
}

// ---------------------------------------------------------------------------
// Launch
// ---------------------------------------------------------------------------
extern "C" void kernel_launch(void* const* d_in, const int* in_sizes, int n_in,
                              void* d_out, int out_size)
{
    const float* f   = (const float*)d_in[0];
    const float* W1  = (const float*)d_in[1];
    const float* b1  = (const float*)d_in[2];
    const float* g1  = (const float*)d_in[3];
    const float* be1 = (const float*)d_in[4];
    const float* W2  = (const float*)d_in[5];
    const float* b2  = (const float*)d_in[6];
    const float* g2  = (const float*)d_in[7];
    const float* be2 = (const float*)d_in[8];
    const float* W3  = (const float*)d_in[9];
    const float* b3  = (const float*)d_in[10];
    float* out = (float*)d_out;

    void *pf, *p1, *p2, *pw1, *pw2, *pw3, *pp, *pp3, *pm;
    cudaGetSymbolAddress(&pf,  g_fhl);
    cudaGetSymbolAddress(&p1,  g_h1hl);
    cudaGetSymbolAddress(&p2,  g_h2hl);
    cudaGetSymbolAddress(&pw1, g_w1hl);
    cudaGetSymbolAddress(&pw2, g_w2hl);
    cudaGetSymbolAddress(&pw3, g_w3hl);
    cudaGetSymbolAddress(&pp,  g_p);
    cudaGetSymbolAddress(&pp3, g_p3);
    cudaGetSymbolAddress(&pm,  g_mask0);
    uint2* fhl  = (uint2*)pf;
    uint2* h1hl = (uint2*)p1;
    uint2* h2hl = (uint2*)p2;
    uint2* w1hl = (uint2*)pw1;
    uint2* w2hl = (uint2*)pw2;
    uint2* w3hl = (uint2*)pw3;
    float* P    = (float*)pp;
    float* P3   = (float*)pp3;
    float* mk   = (float*)pm;

    // noise block bases (65536 total, iteration-ordered):
    //  prep 16000 @0      g1 5000 @16000   r1 2000 @21000
    //  g2   12000 @23000  r2 2000 @35000   g3 14000 @37000
    //  r3    5000 @51000  iter tail 9536 @56000 (iterations 875..1023)
    keys_kernel<<<1, 1024>>>();

    prep_noise<<<4096 + 16000, 256>>>(f, W1, W2, W3, 4096, 0);

    gemm_mma<<<128 + 5000, 256>>>(fhl, w1hl, P, 2048, 8192, 128, 16000);
    reduce_noise<true, 16><<<16 + 2000, 256>>>(P, b1, g1, be1, h1hl, nullptr, 8192, 21000);

    gemm_mma<<<128 + 12000, 256>>>(h1hl, w2hl, P, 8192, 8192, 128, 23000);
    reduce_noise<true, 16><<<16 + 2000, 256>>>(P, b2, g2, be2, h2hl, nullptr, 8192, 35000);

    gemm_mma<<<32 + 14000, 256>>>(h2hl, w3hl, P3, 8192, 2048, 32, 37000);
    reduce_noise<false, 4><<<4 + 5000, 256>>>(P3, b3, nullptr, nullptr, nullptr, mk, 2048, 51000);

    iter_noise<<<64 + 9536, 512>>>(out, 56000);
}

// round 9
// speedup vs baseline: 1.3551x; 1.3551x over previous
#include <cuda_runtime.h>
#include <cstdint>
#include <cstddef>

typedef unsigned long long u64;

// ---------------------------------------------------------------------------
// Device globals (no allocation allowed)
// ---------------------------------------------------------------------------
#define NBLK 65536                                   // noise blocks (1024 iter x 64)
__device__ float g_noise[(size_t)1024 * 131072];     // 512 MiB prescaled gumbel noise
__device__ float g_h1[64 * 8192];
__device__ float g_h2[64 * 8192];
__device__ float g_mask0[64 * 2048];
__device__ float g_p [(size_t)4 * 64 * 8192];        // gemm partials (g1 x4 / g2 x4)
__device__ float g_p3[(size_t)8 * 64 * 2048];        // gemm3 x8 partials
__device__ uint2 g_keys[1024];
__device__ int   g_icnt[1024];                       // per-iteration noise arrivals
__device__ int   g_nq;                               // noise queue head
__device__ int   g_bar[8];                           // phase barrier arrivals

// ---------------------------------------------------------------------------
// f32x2 packed FMA (Blackwell, base PTX)
// ---------------------------------------------------------------------------
#define FMA2(acc, a2, b2) asm("fma.rn.f32x2 %0, %1, %2, %0;" : "+l"(acc) : "l"(a2), "l"(b2))
#define PK2(d, lo, hi)    asm("mov.b64 %0, {%1, %2};" : "=l"(d) : "r"(lo), "r"(hi))
#define UPK2(lo, hi, s)   asm("mov.b64 {%0, %1}, %2;" : "=r"(lo), "=r"(hi) : "l"(s))

__device__ __forceinline__ float ex2f(float x)
{
    float y; asm("ex2.approx.f32 %0, %1;" : "=f"(y) : "f"(x)); return y;
}

// ---------------------------------------------------------------------------
// Threefry-2x32-20 (bit-exact JAX)
// ---------------------------------------------------------------------------
__device__ __forceinline__ void tf_block(uint32_t ks0, uint32_t ks1, uint32_t ks2,
                                         uint32_t x0, uint32_t x1,
                                         uint32_t& o0, uint32_t& o1)
{
    x0 += ks0; x1 += ks1;
#define TFR(r) { x0 += x1; x1 = __funnelshift_l(x1, x1, (r)); x1 ^= x0; }
    TFR(13); TFR(15); TFR(26); TFR(6);
    x0 += ks1; x1 += ks2 + 1u;
    TFR(17); TFR(29); TFR(16); TFR(24);
    x0 += ks2; x1 += ks0 + 2u;
    TFR(13); TFR(15); TFR(26); TFR(6);
    x0 += ks0; x1 += ks1 + 3u;
    TFR(17); TFR(29); TFR(16); TFR(24);
    x0 += ks1; x1 += ks2 + 4u;
    TFR(13); TFR(15); TFR(26); TFR(6);
    x0 += ks2; x1 += ks0 + 5u;
#undef TFR
    o0 = x0; o1 = x1;
}

// init per replay: counters + per-iteration folded keys
__global__ void init_kernel()
{
    const int t = threadIdx.x;
    g_icnt[t] = 0;
    if (t < 8) g_bar[t] = 0;
    if (t == 0) g_nq = 0;
    uint32_t o0, o1;
    tf_block(0u, 42u, 0u ^ 42u ^ 0x1BD11BDAu, 0u, (uint32_t)t, o0, o1);
    g_keys[t] = make_uint2(o0, o1);
}

// bits -> n = -2*log2(-ln u) so the iter loop is e = 2^(mask*C + n), C = 2*log2(e)
__device__ __forceinline__ float bits_to_noise(uint32_t bits)
{
    const uint32_t mant = bits >> 9;
    const float fl = __uint_as_float(0x3F800000u | mant) - 1.0f;  // exact m*2^-23
    float L;
    const float d = 1.0f - fl;
    if (d <= 0.015625f) {
        L = d * (1.0f + d * (0.5f + d * (0.3333333432674408f + d * 0.25f)));
    } else if (mant == 0u) {
        L = 87.336544750553109f;                                  // -ln(2^-126)
    } else {
        L = -0.69314718055994531f * __log2f(fl);
    }
    return -2.0f * __log2f(L);
}

// One noise block = 2048 elements of iteration i = b>>6, chunk b&63. 256 threads.
__device__ __noinline__ void noise_block(int b)
{
    const int tid = threadIdx.x;
    const int i = b >> 6;
    const uint2 key = g_keys[i];
    const uint32_t k1 = key.x, k2 = key.y;
    const uint32_t ks2 = k1 ^ k2 ^ 0x1BD11BDAu;
    const uint32_t jbase = (uint32_t)(b & 63) * 2048u + tid;
    float* out = g_noise + (size_t)i * 131072u;
#pragma unroll
    for (int t = 0; t < 8; t++) {
        uint32_t j = jbase + (uint32_t)t * 256u;
        uint32_t o0, o1;
        tf_block(k1, k2, ks2, 0u, j, o0, o1);
        out[j] = bits_to_noise(o0 ^ o1);
    }
    __syncthreads();
    if (tid == 0) {
        __threadfence();
        atomicAdd(&g_icnt[i], 1);
    }
}

// Pop one noise block (whole CTA). Returns false when queue exhausted.
__device__ __forceinline__ bool try_noise()
{
    __shared__ int s_nb;
    if (threadIdx.x == 0) {
        int b = atomicAdd(&g_nq, 1);
        s_nb = (b < NBLK) ? b : -1;
    }
    __syncthreads();
    const int b = s_nb;
    __syncthreads();
    if (b < 0) return false;
    noise_block(b);
    return true;
}

// Phase barrier: arrive, then generate noise until all CTAs arrived.
__device__ void barrier_fill(int p, int nCTA)
{
    __shared__ int s_done;
    __syncthreads();
    if (threadIdx.x == 0) { __threadfence(); atomicAdd(&g_bar[p], 1); }
    for (;;) {
        if (threadIdx.x == 0)
            s_done = (*(volatile int*)&g_bar[p] >= nCTA) ? 1 : 0;
        __syncthreads();
        if (s_done) break;
        if (!try_noise()) __nanosleep(256);
        __syncthreads();
    }
    __threadfence();
}

// ---------------------------------------------------------------------------
// FFMA2 GEMM tile: 64 rows x 64 cols, Kc of K, 256 thr, 4x4/thread (u64 acc),
// double-buffered smem. Writes raw partials P[kc][64][N].
// ---------------------------------------------------------------------------
__device__ __noinline__ void gemm_tile(const float* __restrict__ X,
                                       const float* __restrict__ W,
                                       float* __restrict__ P,
                                       int K, int N, int cb, int k0, int Kc, int kcIdx)
{
    __shared__ __align__(16) float Xs[2][1024];   // [kk][m]
    __shared__ __align__(16) float Ws[2][1024];   // [kk][n]

    const int tid = threadIdx.x;
    const int tx = tid & 15, ty = tid >> 4;
    const int lm = tid >> 2, lk = (tid & 3) << 2;
    const int wk = tid >> 4, wn = (tid & 15) << 2;

    u64 acc[4][2];
#pragma unroll
    for (int i = 0; i < 4; i++) { acc[i][0] = 0ull; acc[i][1] = 0ull; }

    float4 xa = *(const float4*)(X + (size_t)lm * K + k0 + lk);
    float4 wa = *(const float4*)(W + (size_t)(k0 + wk) * N + cb + wn);
    Xs[0][(lk + 0) * 64 + lm] = xa.x;
    Xs[0][(lk + 1) * 64 + lm] = xa.y;
    Xs[0][(lk + 2) * 64 + lm] = xa.z;
    Xs[0][(lk + 3) * 64 + lm] = xa.w;
    *(float4*)&Ws[0][wk * 64 + wn] = wa;
    __syncthreads();

    const int nt = Kc >> 4;
    int buf = 0;
    for (int t = 0; t < nt; t++) {
        float4 xn, wn4;
        const bool more = (t + 1 < nt);
        if (more) {
            int kk0 = k0 + ((t + 1) << 4);
            xn  = *(const float4*)(X + (size_t)lm * K + kk0 + lk);
            wn4 = *(const float4*)(W + (size_t)(kk0 + wk) * N + cb + wn);
        }
#pragma unroll
        for (int kk = 0; kk < 16; kk++) {
            const float4 a4 = *(const float4*)&Xs[buf][(kk << 6) + (ty << 2)];
            const float4 b4 = *(const float4*)&Ws[buf][(kk << 6) + (tx << 2)];
            u64 bp0, bp1, ad0, ad1, ad2, ad3;
            PK2(bp0, __float_as_uint(b4.x), __float_as_uint(b4.y));
            PK2(bp1, __float_as_uint(b4.z), __float_as_uint(b4.w));
            PK2(ad0, __float_as_uint(a4.x), __float_as_uint(a4.x));
            PK2(ad1, __float_as_uint(a4.y), __float_as_uint(a4.y));
            PK2(ad2, __float_as_uint(a4.z), __float_as_uint(a4.z));
            PK2(ad3, __float_as_uint(a4.w), __float_as_uint(a4.w));
            FMA2(acc[0][0], ad0, bp0); FMA2(acc[0][1], ad0, bp1);
            FMA2(acc[1][0], ad1, bp0); FMA2(acc[1][1], ad1, bp1);
            FMA2(acc[2][0], ad2, bp0); FMA2(acc[2][1], ad2, bp1);
            FMA2(acc[3][0], ad3, bp0); FMA2(acc[3][1], ad3, bp1);
        }
        if (more) {
            const int nb = buf ^ 1;
            Xs[nb][(lk + 0) * 64 + lm] = xn.x;
            Xs[nb][(lk + 1) * 64 + lm] = xn.y;
            Xs[nb][(lk + 2) * 64 + lm] = xn.z;
            Xs[nb][(lk + 3) * 64 + lm] = xn.w;
            *(float4*)&Ws[nb][wk * 64 + wn] = wn4;
            buf = nb;
        }
        __syncthreads();
    }

    float* dst = P + (size_t)kcIdx * 64 * N;
#pragma unroll
    for (int i = 0; i < 4; i++) {
        uint32_t f0, f1, f2, f3;
        UPK2(f0, f1, acc[i][0]);
        UPK2(f2, f3, acc[i][1]);
        float4 o = make_float4(__uint_as_float(f0), __uint_as_float(f1),
                               __uint_as_float(f2), __uint_as_float(f3));
        *(float4*)(dst + (size_t)((ty << 2) + i) * N + cb + (tx << 2)) = o;
    }
}

// ---------------------------------------------------------------------------
// K-split reduce + bias + batch-BN (+ affine + ReLU). 2 cols/thread.
// ---------------------------------------------------------------------------
template <int S, bool AR>
__device__ __noinline__ void reduce_tile(const float* __restrict__ P,
                                         const float* __restrict__ bias,
                                         const float* __restrict__ gamma,
                                         const float* __restrict__ beta,
                                         float* __restrict__ Y, int N, int cta)
{
    const int cp = cta * 256 + threadIdx.x;
    const int c0 = cp * 2;
    const float b0 = bias[c0], b1 = bias[c0 + 1];
    float s0 = 0.f, ss0 = 0.f, s1 = 0.f, ss1 = 0.f;
#pragma unroll 4
    for (int r = 0; r < 64; r++) {
        float v0 = b0, v1 = b1;
#pragma unroll
        for (int q = 0; q < S; q++) {
            float2 v = *(const float2*)(P + ((size_t)q * 64 + r) * N + c0);
            v0 += v.x; v1 += v.y;
        }
        s0 += v0; ss0 += v0 * v0;
        s1 += v1; ss1 += v1 * v1;
    }
    const float m0 = s0 * 0.015625f, m1 = s1 * 0.015625f;
    const float i0 = rsqrtf(fmaf(-m0, m0, ss0 * 0.015625f) + 1e-5f);
    const float i1 = rsqrtf(fmaf(-m1, m1, ss1 * 0.015625f) + 1e-5f);
    const float ga0 = AR ? gamma[c0] : 1.0f, ga1 = AR ? gamma[c0 + 1] : 1.0f;
    const float be0 = AR ? beta[c0]  : 0.0f, be1 = AR ? beta[c0 + 1]  : 0.0f;
#pragma unroll 4
    for (int r = 0; r < 64; r++) {
        float v0 = b0, v1 = b1;
#pragma unroll
        for (int q = 0; q < S; q++) {
            float2 v = *(const float2*)(P + ((size_t)q * 64 + r) * N + c0);
            v0 += v.x; v1 += v.y;
        }
        float y0 = (v0 - m0) * i0;
        float y1 = (v1 - m1) * i1;
        if (AR) {
            y0 = fmaxf(fmaf(y0, ga0, be0), 0.0f);
            y1 = fmaxf(fmaf(y1, ga1, be1), 0.0f);
        }
        *(float2*)(Y + (size_t)r * N + c0) = make_float2(y0, y1);
    }
}

// ---------------------------------------------------------------------------
// Gumbel-softmax-max chain: one CTA per row, 256 thr, 8 cols/thread.
// Gated on g_icnt (noise may still be generating in other CTAs).
// ---------------------------------------------------------------------------
__device__ __noinline__ void iter_row(float* __restrict__ zout, int row)
{
    __shared__ __align__(16) float wsum[2][8];
    const int tid = threadIdx.x;
    const int lane = tid & 31, wid = tid >> 5;
    const float C = 2.8853900817779268f;   // 2*log2(e)

    float4 ma = *(const float4*)(g_mask0 + row * 2048 + 8 * tid);
    float4 mb = *(const float4*)(g_mask0 + row * 2048 + 8 * tid + 4);
    float4 za = make_float4(0.f, 0.f, 0.f, 0.f);
    float4 zb = make_float4(0.f, 0.f, 0.f, 0.f);

    volatile int* icnt = (volatile int*)g_icnt;
    const float4* np = (const float4*)g_noise + (size_t)row * 512 + 2 * tid;

    if (tid == 0) {
        while (icnt[0] < 64) __nanosleep(128);
        __threadfence();
    }
    __syncthreads();
    float4 na = np[0], nb = np[1];

    for (int i = 0; i < 1024; i++) {
        const float4 ca = na, cb = nb;

        const float e0 = ex2f(fmaf(ma.x, C, ca.x));
        const float e1 = ex2f(fmaf(ma.y, C, ca.y));
        const float e2 = ex2f(fmaf(ma.z, C, ca.z));
        const float e3 = ex2f(fmaf(ma.w, C, ca.w));
        const float e4 = ex2f(fmaf(mb.x, C, cb.x));
        const float e5 = ex2f(fmaf(mb.y, C, cb.y));
        const float e6 = ex2f(fmaf(mb.z, C, cb.z));
        const float e7 = ex2f(fmaf(mb.w, C, cb.w));
        float s = ((e0 + e1) + (e2 + e3)) + ((e4 + e5) + (e6 + e7));
#pragma unroll
        for (int o = 16; o; o >>= 1) s += __shfl_xor_sync(0xffffffffu, s, o);
        if (lane == 0) wsum[i & 1][wid] = s;

        // readiness watermark: ensure iterations [i+1, i+33] are complete
        if (tid == 0 && (i & 31) == 0) {
            const int hi = (i + 33 < 1023) ? i + 33 : 1023;
            for (;;) {
                int ok = 1;
                for (int w = i + 1; w <= hi; w++) ok &= (icnt[w] >= 64);
                if (ok) break;
                __nanosleep(256);
            }
            __threadfence();
        }
        __syncthreads();

        const float4* wp = (const float4*)wsum[i & 1];
        const float4 t0 = wp[0], t1 = wp[1];
        const float tt = ((t0.x + t0.y) + (t0.z + t0.w)) + ((t1.x + t1.y) + (t1.z + t1.w));
        float r; asm("rcp.approx.f32 %0, %1;" : "=f"(r) : "f"(tt));
        ma.x = e0 * r; ma.y = e1 * r; ma.z = e2 * r; ma.w = e3 * r;
        mb.x = e4 * r; mb.y = e5 * r; mb.z = e6 * r; mb.w = e7 * r;
        za.x = fmaxf(za.x, ma.x); za.y = fmaxf(za.y, ma.y);
        za.z = fmaxf(za.z, ma.z); za.w = fmaxf(za.w, ma.w);
        zb.x = fmaxf(zb.x, mb.x); zb.y = fmaxf(zb.y, mb.y);
        zb.z = fmaxf(zb.z, mb.z); zb.w = fmaxf(zb.w, mb.w);

        if (i < 1023) {
            na = np[(size_t)(i + 1) * 32768];
            nb = np[(size_t)(i + 1) * 32768 + 1];
        }
    }
    *(float4*)(zout + row * 2048 + 8 * tid)     = za;
    *(float4*)(zout + row * 2048 + 8 * tid + 4) = zb;
}

// ---------------------------------------------------------------------------
// The persistent fused kernel: all phases, noise fills every bubble.
// ---------------------------------------------------------------------------
__global__ __launch_bounds__(256, 3) void fused(const float* __restrict__ f,
                                                const float* __restrict__ W1,
                                                const float* __restrict__ b1,
                                                const float* __restrict__ g1,
                                                const float* __restrict__ be1,
                                                const float* __restrict__ W2,
                                                const float* __restrict__ b2,
                                                const float* __restrict__ g2,
                                                const float* __restrict__ be2,
                                                const float* __restrict__ W3,
                                                const float* __restrict__ b3,
                                                float* __restrict__ out,
                                                int nCTA)
{
    const int cta = blockIdx.x;

    // gemmers: 2 of every 3 CTAs; the rest generate noise at the barriers
    const bool isG = (cta % 3) != 2;
    const int gidx = cta - cta / 3 - ((cta % 3) == 2 ? 1 : 0);
    const int nG   = nCTA - (nCTA + 1) / 3;   // number of gemmer CTAs

    // P0: gemm1  (K=2048, split 4 -> 512 tiles, Kc=512, 128 col tiles)
    if (isG)
        for (int t = gidx; t < 512; t += nG)
            gemm_tile(f, W1, g_p, 2048, 8192, (t & 127) * 64, (t >> 7) * 512, 512, t >> 7);
    barrier_fill(0, nCTA);

    // P1: reduce1 -> h1
    if (cta < 16) reduce_tile<4, true>(g_p, b1, g1, be1, g_h1, 8192, cta);
    barrier_fill(1, nCTA);

    // P2: gemm2  (K=8192, split 4 -> 512 tiles, Kc=2048)
    if (isG)
        for (int t = gidx; t < 512; t += nG)
            gemm_tile(g_h1, W2, g_p, 8192, 8192, (t & 127) * 64, (t >> 7) * 2048, 2048, t >> 7);
    barrier_fill(2, nCTA);

    // P3: reduce2 -> h2
    if (cta < 16) reduce_tile<4, true>(g_p, b2, g2, be2, g_h2, 8192, cta);
    barrier_fill(3, nCTA);

    // P4: gemm3  (K=8192, split 8 -> 256 tiles, Kc=1024, 32 col tiles)
    if (isG)
        for (int t = gidx; t < 256; t += nG)
            gemm_tile(g_h2, W3, g_p3, 8192, 2048, (t & 31) * 64, (t >> 5) * 1024, 1024, t >> 5);
    barrier_fill(4, nCTA);

    // P5: reduce3 -> mask0 (no affine)
    if (cta < 4) reduce_tile<8, false>(g_p3, b3, nullptr, nullptr, g_mask0, 2048, cta);
    barrier_fill(5, nCTA);

    // P6: iteration chains on 64 CTAs; everyone else drains the noise queue
    if (cta < 64) {
        iter_row(out, cta);
    } else {
        while (try_noise()) {}
    }
}

// ---------------------------------------------------------------------------
// Launch
// ---------------------------------------------------------------------------
extern "C" void kernel_launch(void* const* d_in, const int* in_sizes, int n_in,
                              void* d_out, int out_size)
{
    const float* f   = (const float*)d_in[0];
    const float* W1  = (const float*)d_in[1];
    const float* b1  = (const float*)d_in[2];
    const float* g1  = (const float*)d_in[3];
    const float* be1 = (const float*)d_in[4];
    const float* W2  = (const float*)d_in[5];
    const float* b2  = (const float*)d_in[6];
    const float* g2  = (const float*)d_in[7];
    const float* be2 = (const float*)d_in[8];
    const float* W3  = (const float*)d_in[9];
    const float* b3  = (const float*)d_in[10];
    float* out = (float*)d_out;

    int dev = 0;
    cudaGetDevice(&dev);
    int sms = 0;
    cudaDeviceGetAttribute(&sms, cudaDevAttrMultiProcessorCount, dev);
    int occ = 0;
    cudaOccupancyMaxActiveBlocksPerMultiprocessor(&occ, fused, 256, 0);
    if (occ < 1) occ = 1;
    if (occ > 3) occ = 3;
    int nCTA = sms * occ;

    init_kernel<<<1, 1024>>>();
    fused<<<nCTA, 256>>>(f, W1, b1, g1, be1, W2, b2, g2, be2, W3, b3, out, nCTA);
}